// round 14
// baseline (speedup 1.0000x reference)
#include <cuda_runtime.h>
#include <cuda_fp16.h>
#include <cstdint>

// ---------------- problem constants ----------------
#define NUM_E    64
#define IN_F     512
#define OUT_F    512
#define NTOK     131072
#define CAPACITY 3072

// ---------------- tiling ----------------
#define TM 128
#define TN 128
#define KC 32                  // K chunk (32 fp16 = 64B row)
#define NCH (IN_F / KC)        // 16
#define THREADS 256            // 8 warps, warp tile 64x32 (2 M-groups x 4 N-groups)
#define NSTAGE 6
#define NTILES (OUT_F / TN)    // 4
#define MTILES (CAPACITY / TM) // 24

// ---------------- smem layout (bytes) ----------------
#define SM_TOK   0                       // 128 ints
#define SM_BIAS  512                     // 128 floats
#define SM_BUF   1024
#define TILE_X   (TM * KC * 2)           // 8192
#define TILE_W   (TN * KC * 2)           // 8192
#define STG_SZ   (TILE_X + TILE_W)       // 16384
#define SMEM_TOTAL (SM_BUF + NSTAGE * STG_SZ)   // 99328 (x2 CTAs = 194KB)

#define ACCW 132                          // padded epilogue stride (floats)

// SW64 swizzle for 64B rows
#define SWZ64(off) ((off) ^ (((off) >> 3) & 0x30))

__device__ int g_cnt[NUM_E];              // zero at module load; k_gemm re-zeroes
__device__ int g_done;                    // k_gemm completion ticket
__device__ int g_tok[NUM_E * CAPACITY];   // slot -> token id

// fp16 operands: xg permuted by expert slot; wf expert-major
__device__ __half g_xg[(size_t)NUM_E * CAPACITY * IN_F]; // 192 MB
__device__ __half g_wf[(size_t)NUM_E * OUT_F * IN_F];    // 32 MB

// ---------------- PTX helpers ----------------
__device__ __forceinline__ uint32_t smem_u32(const void* p) {
    uint32_t a;
    asm("{ .reg .u64 t; cvta.to.shared.u64 t, %1; cvt.u32.u64 %0, t; }"
        : "=r"(a) : "l"(p));
    return a;
}
__device__ __forceinline__ void cp16(uint32_t dst, const void* src) {
    asm volatile("cp.async.cg.shared.global [%0], [%1], 16;"
                 :: "r"(dst), "l"(src));
}
__device__ __forceinline__ void cp_commit() {
    asm volatile("cp.async.commit_group;" ::: "memory");
}
template <int N>
__device__ __forceinline__ void cp_wait() {
    asm volatile("cp.async.wait_group %0;" :: "n"(N) : "memory");
}
__device__ __forceinline__ void ldsm4(uint32_t* r, uint32_t a) {
    asm volatile("ldmatrix.sync.aligned.m8n8.x4.shared.b16 {%0,%1,%2,%3}, [%4];"
                 : "=r"(r[0]), "=r"(r[1]), "=r"(r[2]), "=r"(r[3]) : "r"(a));
}
__device__ __forceinline__ void mma16816(float* d, const uint32_t* a,
                                         const uint32_t* b) {
    asm volatile(
        "mma.sync.aligned.m16n8k16.row.col.f32.f16.f16.f32 "
        "{%0,%1,%2,%3}, {%4,%5,%6,%7}, {%8,%9}, {%0,%1,%2,%3};"
        : "+f"(d[0]), "+f"(d[1]), "+f"(d[2]), "+f"(d[3])
        : "r"(a[0]), "r"(a[1]), "r"(a[2]), "r"(a[3]), "r"(b[0]), "r"(b[1]));
}

// fp32x16 -> fp16x16 pack
__device__ __forceinline__ void cvt16(const float4* v, uint32_t* H) {
    const float* f = (const float*)v;
#pragma unroll
    for (int j = 0; j < 8; j++) {
        __half h0 = __float2half_rn(f[2 * j]);
        __half h1 = __float2half_rn(f[2 * j + 1]);
        H[j] = ((uint32_t)__half_as_ushort(h1) << 16) | __half_as_ushort(h0);
    }
}

// ---------------- fused prep: route blocks + w-cvt blocks in one grid ------
// Blocks [0, ROUTE_BLKS): token routing + x fp32->fp16 permuted write.
// Blocks [ROUTE_BLKS, ...): w fp32->fp16 conversion.
// g_cnt starts zeroed (module init on first call; k_gemm re-zeroes after).
#define RBLK 256
#define ROUTE_BLKS (NTOK / RBLK)                 // 512
#define WCVT_N16   (NUM_E * OUT_F * IN_F / 16)   // 1048576
#define WCVT_BLKS  (WCVT_N16 / 256)              // 4096

__global__ __launch_bounds__(256)
void k_prep(const float* __restrict__ x, const int* __restrict__ eid,
            const float* __restrict__ wsrc, float* __restrict__ out) {
    const int tid = threadIdx.x;

    if (blockIdx.x >= ROUTE_BLKS) {
        // ---- w-cvt part ----
        int g = (blockIdx.x - ROUTE_BLKS) * 256 + tid;
        const float4* s = (const float4*)(wsrc + (size_t)g * 16);
        float4 v[4] = {s[0], s[1], s[2], s[3]};
        uint32_t H[8];
        cvt16(v, H);
        uint4* d = (uint4*)(g_wf + (size_t)g * 16);
        d[0] = make_uint4(H[0], H[1], H[2], H[3]);
        d[1] = make_uint4(H[4], H[5], H[6], H[7]);
        return;
    }

    // ---- route part ----
    __shared__ int s_slot[RBLK];
    __shared__ int s_hist[NUM_E];
    __shared__ int s_base[NUM_E];
    __shared__ int s_cur[NUM_E];

    const int t0 = blockIdx.x * RBLK;

    int e = eid[t0 + tid];
    if (tid < NUM_E) { s_hist[tid] = 0; s_cur[tid] = 0; }
    __syncthreads();
    atomicAdd(&s_hist[e], 1);
    __syncthreads();
    if (tid < NUM_E) {
        int h = s_hist[tid];
        s_base[tid] = h ? atomicAdd(&g_cnt[tid], h) : 0;
    }
    __syncthreads();
    {
        int r = s_base[e] + atomicAdd(&s_cur[e], 1);
        if (r < CAPACITY) {
            int slot = e * CAPACITY + r;
            g_tok[slot] = t0 + tid;
            s_slot[tid] = slot;
        } else {
            s_slot[tid] = -1;
        }
    }
    __syncthreads();

    const int lane = tid & 31;
    const int wrp  = tid >> 5;
    const float* xw = x + (size_t)(t0 + wrp * 32) * IN_F + lane * 16;

#pragma unroll 4
    for (int i = 0; i < 32; i++) {
        const int row  = wrp * 32 + i;
        const int slot = s_slot[row];
        const float4* src = (const float4*)(xw + (size_t)i * IN_F);
        if (slot >= 0) {
            float4 v[4] = {__ldcs(src), __ldcs(src + 1),
                           __ldcs(src + 2), __ldcs(src + 3)};
            uint32_t H[8];
            cvt16(v, H);
            uint4* d = (uint4*)(g_xg + (size_t)slot * IN_F + lane * 16);
            d[0] = make_uint4(H[0], H[1], H[2], H[3]);
            d[1] = make_uint4(H[4], H[5], H[6], H[7]);
        } else {
            float4 z = make_float4(0.f, 0.f, 0.f, 0.f);
            float4* o = (float4*)(out + (size_t)(t0 + row) * OUT_F + lane * 16);
            o[0] = z; o[1] = z; o[2] = z; o[3] = z;
        }
    }
}

// ---------------- main GEMM: 128x128 tile, 8 warps (64x32), 2 CTAs/SM ----------------
__global__ __launch_bounds__(THREADS, 2)
void k_gemm(const float* __restrict__ bias, float* __restrict__ out) {
    extern __shared__ char smem[];

    const int e = blockIdx.y;
    int cnt = g_cnt[e];
    if (cnt > CAPACITY) cnt = CAPACITY;
    const int m0 = (blockIdx.x >> 2) * TM;
    const int n0 = (blockIdx.x & 3) * TN;

    const int tid  = threadIdx.x;
    const int lane = tid & 31;
    const int wid  = tid >> 5;

    int*   stok  = (int*)(smem + SM_TOK);
    float* sbias = (float*)(smem + SM_BIAS);

    if (tid < TM) {
        stok[tid] = (m0 + tid < cnt) ? g_tok[e * CAPACITY + m0 + tid] : 0;
    } else {
        sbias[tid - TM] = bias[e * OUT_F + n0 + (tid - TM)];
    }
    __syncthreads();   // all threads have read g_cnt[e] (and g_tok) by here

    // completion ticket: last block to arrive re-zeroes g_cnt for next replay
    if (tid == 0) {
        __threadfence();
        int done = atomicAdd(&g_done, 1);
        if (done == (int)(gridDim.x * gridDim.y) - 1) {
#pragma unroll
            for (int i = 0; i < NUM_E; i++) g_cnt[i] = 0;
            __threadfence();
            g_done = 0;
        }
    }

    if (m0 >= cnt) return;

    const uint32_t sb = smem_u32(smem);
    const size_t xrow0 = (size_t)(e * CAPACITY + m0) * IN_F;
    const size_t wrow0 = ((size_t)e * OUT_F + n0) * IN_F;

    // cp.async: 1024 x 16B granules per stage (X 512 + W 512), 4 per thread
    auto issue = [&](int c, int st) {
        const uint32_t stg = sb + SM_BUF + st * STG_SZ;
        const int k0 = c * KC;
#pragma unroll
        for (int i = 0; i < 4; i++) {
            int g = tid + i * THREADS;              // 0..1023
            if (g < 512) {
                int row = g >> 2, c4 = g & 3;
                uint32_t dst = stg + SWZ64((uint32_t)(row * 64 + c4 * 16));
                cp16(dst, g_xg + xrow0 + (size_t)row * IN_F + k0 + c4 * 8);
            } else {
                int gw = g - 512;
                int row = gw >> 2, c4 = gw & 3;
                uint32_t dst = stg + TILE_X + SWZ64((uint32_t)(row * 64 + c4 * 16));
                cp16(dst, g_wf + wrow0 + (size_t)row * IN_F + k0 + c4 * 8);
            }
        }
        cp_commit();
    };

    // per-warp ldmatrix address precompute (stage-relative, 64B rows)
    const int aw = (wid >> 2) * 64;  // warp M offset: 2 groups of 64
    const int bw = (wid & 3) * 32;   // warp N offset: 4 groups of 32

    uint32_t a_off[4], a_mask[4];
    {
        int ar = lane & 15;
#pragma unroll
        for (int fi = 0; fi < 4; fi++) {
            int r = aw + fi * 16 + ar;
            a_off[fi] = (uint32_t)(r * 64);
            a_mask[fi] = ((r >> 1) & 3) * 16;
        }
    }
    const uint32_t a_klane = (lane & 16) ? 16u : 0u;

    uint32_t b_off[2], b_mask[2];
    {
        int br = (lane & 7) + ((lane & 16) ? 8 : 0);
#pragma unroll
        for (int jp = 0; jp < 2; jp++) {
            int r = bw + jp * 16 + br;
            b_off[jp] = (uint32_t)(TILE_X + r * 64);
            b_mask[jp] = ((r >> 1) & 3) * 16;
        }
    }
    const uint32_t b_klane = (lane & 8) ? 16u : 0u;

    float acc[4][4][4];
#pragma unroll
    for (int i = 0; i < 4; i++)
#pragma unroll
        for (int j = 0; j < 4; j++)
#pragma unroll
            for (int q = 0; q < 4; q++) acc[i][j][q] = 0.f;

    // ---- pipeline: 6 buffers, 5 chunks in flight ----
    issue(0, 0);
    issue(1, 1);
    issue(2, 2);
    issue(3, 3);
    issue(4, 4);

#pragma unroll
    for (int c = 0; c < NCH; c++) {
        if (c <= NCH - 5)      cp_wait<4>();
        else if (c == NCH - 4) cp_wait<3>();
        else if (c == NCH - 3) cp_wait<2>();
        else if (c == NCH - 2) cp_wait<1>();
        else                   cp_wait<0>();
        __syncthreads();   // stage c fully visible to all warps

        if (c + 5 < NCH) issue(c + 5, (c + 5) % NSTAGE);

        const uint32_t stg = sb + SM_BUF + (c % NSTAGE) * STG_SZ;

#pragma unroll
        for (int s = 0; s < 2; s++) {
            uint32_t xf[4][4], wf[2][4];
            const uint32_t kcol = (uint32_t)(s * 32);
#pragma unroll
            for (int fi = 0; fi < 4; fi++)
                ldsm4(xf[fi], stg + a_off[fi] + ((kcol + a_klane) ^ a_mask[fi]));
#pragma unroll
            for (int jp = 0; jp < 2; jp++)
                ldsm4(wf[jp], stg + b_off[jp] + ((kcol + b_klane) ^ b_mask[jp]));
#pragma unroll
            for (int fi = 0; fi < 4; fi++) {
#pragma unroll
                for (int j = 0; j < 4; j++) {
                    mma16816(acc[fi][j], xf[fi], &wf[j >> 1][(j & 1) * 2]);
                }
            }
        }
    }

    // ---- epilogue: stage acc through smem for coalesced scatter ----
    __syncthreads();
    float* sacc = (float*)(smem + SM_BUF);
    {
        const int r0 = aw + (lane >> 2);
        const int c0 = bw + 2 * (lane & 3);
#pragma unroll
        for (int fi = 0; fi < 4; fi++) {
#pragma unroll
            for (int j = 0; j < 4; j++) {
                int rr = r0 + fi * 16;
                int cc = c0 + j * 8;
                sacc[rr * ACCW + cc]           = acc[fi][j][0];
                sacc[rr * ACCW + cc + 1]       = acc[fi][j][1];
                sacc[(rr + 8) * ACCW + cc]     = acc[fi][j][2];
                sacc[(rr + 8) * ACCW + cc + 1] = acc[fi][j][3];
            }
        }
    }
    __syncthreads();

    {
        const int row = tid >> 1;                 // 0..127
        const int q   = (tid & 1) * 64;           // half of 128 cols
        if (m0 + row < cnt) {
            const int tok = stok[row];
            float* op = out + (size_t)tok * OUT_F + n0 + q;
            const float* sr = &sacc[row * ACCW + q];
#pragma unroll
            for (int i = 0; i < 16; i++) {
                float4 v = *(const float4*)(sr + i * 4);
                v.x += sbias[q + i * 4 + 0];
                v.y += sbias[q + i * 4 + 1];
                v.z += sbias[q + i * 4 + 2];
                v.w += sbias[q + i * 4 + 3];
                __stcs((float4*)(op + i * 4), v);
            }
        }
    }
}

// ---------------- launch ----------------
extern "C" void kernel_launch(void* const* d_in, const int* in_sizes, int n_in,
                              void* d_out, int out_size) {
    const float* x    = (const float*)d_in[0];
    const float* wght = (const float*)d_in[1];
    const float* bias = (const float*)d_in[2];
    const int*   eid  = (const int*)d_in[3];
    float* out = (float*)d_out;

    cudaFuncSetAttribute(k_gemm, cudaFuncAttributeMaxDynamicSharedMemorySize,
                         SMEM_TOTAL);

    // fused route + w-cvt (g_cnt is zero: module init / re-zeroed by k_gemm)
    k_prep<<<ROUTE_BLKS + WCVT_BLKS, 256>>>(x, eid, wght, out);

    dim3 grid(MTILES * NTILES, NUM_E);
    k_gemm<<<grid, THREADS, SMEM_TOTAL>>>(bias, out);
}

// round 15
// speedup vs baseline: 1.3185x; 1.3185x over previous
#include <cuda_runtime.h>
#include <cuda_fp16.h>
#include <cstdint>

// ---------------- problem constants ----------------
#define NUM_E    64
#define IN_F     512
#define OUT_F    512
#define NTOK     131072
#define CAPACITY 3072

// ---------------- tiling ----------------
#define TM 128
#define TN 128
#define KC 32                  // K chunk (32 fp16 = 64B row)
#define NCH (IN_F / KC)        // 16
#define THREADS 256            // 8 warps, warp tile 64x32 (2 M-groups x 4 N-groups)
#define NSTAGE 6
#define NTILES (OUT_F / TN)    // 4
#define MTILES (CAPACITY / TM) // 24

// ---------------- smem layout (bytes) ----------------
#define SM_TOK   0                       // 128 ints
#define SM_BIAS  512                     // 128 floats
#define SM_BUF   1024
#define TILE_X   (TM * KC * 2)           // 8192
#define TILE_W   (TN * KC * 2)           // 8192
#define STG_SZ   (TILE_X + TILE_W)       // 16384
#define SMEM_TOTAL (SM_BUF + NSTAGE * STG_SZ)   // 99328 (x2 CTAs = 194KB)

// SW64 swizzle for 64B rows
#define SWZ64(off) ((off) ^ (((off) >> 3) & 0x30))

__device__ int g_cnt[NUM_E];
__device__ int g_tok[NUM_E * CAPACITY];   // slot -> token id

// fp16 operands: xg permuted by expert slot; wf expert-major
__device__ __half g_xg[(size_t)NUM_E * CAPACITY * IN_F]; // 192 MB
__device__ __half g_wf[(size_t)NUM_E * OUT_F * IN_F];    // 32 MB

// ---------------- PTX helpers ----------------
__device__ __forceinline__ uint32_t smem_u32(const void* p) {
    uint32_t a;
    asm("{ .reg .u64 t; cvta.to.shared.u64 t, %1; cvt.u32.u64 %0, t; }"
        : "=r"(a) : "l"(p));
    return a;
}
__device__ __forceinline__ void cp16(uint32_t dst, const void* src) {
    asm volatile("cp.async.cg.shared.global [%0], [%1], 16;"
                 :: "r"(dst), "l"(src));
}
__device__ __forceinline__ void cp_commit() {
    asm volatile("cp.async.commit_group;" ::: "memory");
}
template <int N>
__device__ __forceinline__ void cp_wait() {
    asm volatile("cp.async.wait_group %0;" :: "n"(N) : "memory");
}
__device__ __forceinline__ void ldsm4(uint32_t* r, uint32_t a) {
    asm volatile("ldmatrix.sync.aligned.m8n8.x4.shared.b16 {%0,%1,%2,%3}, [%4];"
                 : "=r"(r[0]), "=r"(r[1]), "=r"(r[2]), "=r"(r[3]) : "r"(a));
}
__device__ __forceinline__ void mma16816(float* d, const uint32_t* a,
                                         const uint32_t* b) {
    asm volatile(
        "mma.sync.aligned.m16n8k16.row.col.f32.f16.f16.f32 "
        "{%0,%1,%2,%3}, {%4,%5,%6,%7}, {%8,%9}, {%0,%1,%2,%3};"
        : "+f"(d[0]), "+f"(d[1]), "+f"(d[2]), "+f"(d[3])
        : "r"(a[0]), "r"(a[1]), "r"(a[2]), "r"(a[3]), "r"(b[0]), "r"(b[1]));
}

// fp32x16 -> fp16x16 pack
__device__ __forceinline__ void cvt16(const float4* v, uint32_t* H) {
    const float* f = (const float*)v;
#pragma unroll
    for (int j = 0; j < 8; j++) {
        __half h0 = __float2half_rn(f[2 * j]);
        __half h1 = __float2half_rn(f[2 * j + 1]);
        H[j] = ((uint32_t)__half_as_ushort(h1) << 16) | __half_as_ushort(h0);
    }
}

// ---------------- zero counters ----------------
__global__ void k_zero() {
    if (threadIdx.x < NUM_E) g_cnt[threadIdx.x] = 0;
}

// ---------------- fused route + x->fp16 permuted write ----------------
#define RBLK 256
__global__ __launch_bounds__(RBLK)
void k_route(const float* __restrict__ x, const int* __restrict__ eid,
             float* __restrict__ out) {
    __shared__ int s_slot[RBLK];
    __shared__ int s_hist[NUM_E];
    __shared__ int s_base[NUM_E];
    __shared__ int s_cur[NUM_E];

    const int tid = threadIdx.x;
    const int t0  = blockIdx.x * RBLK;

    int e = eid[t0 + tid];
    if (tid < NUM_E) { s_hist[tid] = 0; s_cur[tid] = 0; }
    __syncthreads();
    atomicAdd(&s_hist[e], 1);
    __syncthreads();
    if (tid < NUM_E) {
        int h = s_hist[tid];
        s_base[tid] = h ? atomicAdd(&g_cnt[tid], h) : 0;
    }
    __syncthreads();
    {
        int r = s_base[e] + atomicAdd(&s_cur[e], 1);
        if (r < CAPACITY) {
            int slot = e * CAPACITY + r;
            g_tok[slot] = t0 + tid;
            s_slot[tid] = slot;
        } else {
            s_slot[tid] = -1;
        }
    }
    __syncthreads();

    const int lane = tid & 31;
    const int wrp  = tid >> 5;
#pragma unroll 4
    for (int i = 0; i < 32; i++) {
        const int row = wrp * 32 + i;
        const int slot = s_slot[row];
        const float* src = x + (size_t)(t0 + row) * IN_F + lane * 16;
        if (slot >= 0) {
            float4 v[4] = {*(const float4*)(src + 0), *(const float4*)(src + 4),
                           *(const float4*)(src + 8), *(const float4*)(src + 12)};
            uint32_t H[8];
            cvt16(v, H);
            uint4* d = (uint4*)(g_xg + (size_t)slot * IN_F + lane * 16);
            d[0] = make_uint4(H[0], H[1], H[2], H[3]);
            d[1] = make_uint4(H[4], H[5], H[6], H[7]);
        } else {
            float4 z = make_float4(0.f, 0.f, 0.f, 0.f);
            float4* o = (float4*)(out + (size_t)(t0 + row) * OUT_F + lane * 16);
            o[0] = z; o[1] = z; o[2] = z; o[3] = z;
        }
    }
}

// ---------------- pre-pass: w -> fp16 ----------------
__global__ __launch_bounds__(256)
void k_cvt(const float* __restrict__ src, __half* __restrict__ dst, int n16) {
    int g = blockIdx.x * blockDim.x + threadIdx.x;
    if (g >= n16) return;
    const float4* s = (const float4*)(src + (size_t)g * 16);
    float4 v[4] = {s[0], s[1], s[2], s[3]};
    uint32_t H[8];
    cvt16(v, H);
    uint4* d = (uint4*)(dst + (size_t)g * 16);
    d[0] = make_uint4(H[0], H[1], H[2], H[3]);
    d[1] = make_uint4(H[4], H[5], H[6], H[7]);
}

// ---------------- main GEMM: 128x128 tile, 8 warps (64x32), 2 CTAs/SM ----------------
__global__ __launch_bounds__(THREADS, 2)
void k_gemm(const float* __restrict__ bias, float* __restrict__ out) {
    extern __shared__ char smem[];

    const int e = blockIdx.y;
    int cnt = g_cnt[e];
    if (cnt > CAPACITY) cnt = CAPACITY;
    const int m0 = (blockIdx.x >> 2) * TM;
    if (m0 >= cnt) return;
    const int n0 = (blockIdx.x & 3) * TN;

    const int tid  = threadIdx.x;
    const int lane = tid & 31;
    const int wid  = tid >> 5;

    int*   stok  = (int*)(smem + SM_TOK);
    float* sbias = (float*)(smem + SM_BIAS);

    if (tid < TM) {
        stok[tid] = (m0 + tid < cnt) ? g_tok[e * CAPACITY + m0 + tid] : 0;
    } else {
        sbias[tid - TM] = bias[e * OUT_F + n0 + (tid - TM)];
    }
    __syncthreads();

    const uint32_t sb = smem_u32(smem);
    const size_t xrow0 = (size_t)(e * CAPACITY + m0) * IN_F;
    const size_t wrow0 = ((size_t)e * OUT_F + n0) * IN_F;

    // cp.async: 1024 x 16B granules per stage (X 512 + W 512), 4 per thread
    auto issue = [&](int c, int st) {
        const uint32_t stg = sb + SM_BUF + st * STG_SZ;
        const int k0 = c * KC;
#pragma unroll
        for (int i = 0; i < 4; i++) {
            int g = tid + i * THREADS;              // 0..1023
            if (g < 512) {
                int row = g >> 2, c4 = g & 3;
                uint32_t dst = stg + SWZ64((uint32_t)(row * 64 + c4 * 16));
                cp16(dst, g_xg + xrow0 + (size_t)row * IN_F + k0 + c4 * 8);
            } else {
                int gw = g - 512;
                int row = gw >> 2, c4 = gw & 3;
                uint32_t dst = stg + TILE_X + SWZ64((uint32_t)(row * 64 + c4 * 16));
                cp16(dst, g_wf + wrow0 + (size_t)row * IN_F + k0 + c4 * 8);
            }
        }
        cp_commit();
    };

    // per-warp ldmatrix address precompute (stage-relative, 64B rows)
    const int aw = (wid >> 2) * 64;  // warp M offset: 2 groups of 64
    const int bw = (wid & 3) * 32;   // warp N offset: 4 groups of 32

    uint32_t a_off[4], a_mask[4];
    {
        int ar = lane & 15;
#pragma unroll
        for (int fi = 0; fi < 4; fi++) {
            int r = aw + fi * 16 + ar;
            a_off[fi] = (uint32_t)(r * 64);
            a_mask[fi] = ((r >> 1) & 3) * 16;
        }
    }
    const uint32_t a_klane = (lane & 16) ? 16u : 0u;

    uint32_t b_off[2], b_mask[2];
    {
        int br = (lane & 7) + ((lane & 16) ? 8 : 0);
#pragma unroll
        for (int jp = 0; jp < 2; jp++) {
            int r = bw + jp * 16 + br;
            b_off[jp] = (uint32_t)(TILE_X + r * 64);
            b_mask[jp] = ((r >> 1) & 3) * 16;
        }
    }
    const uint32_t b_klane = (lane & 8) ? 16u : 0u;

    float acc[4][4][4];
#pragma unroll
    for (int i = 0; i < 4; i++)
#pragma unroll
        for (int j = 0; j < 4; j++)
#pragma unroll
            for (int q = 0; q < 4; q++) acc[i][j][q] = 0.f;

    // ---- pipeline: 6 buffers, 5 chunks in flight ----
    issue(0, 0);
    issue(1, 1);
    issue(2, 2);
    issue(3, 3);
    issue(4, 4);

#pragma unroll
    for (int c = 0; c < NCH; c++) {
        if (c <= NCH - 5)      cp_wait<4>();
        else if (c == NCH - 4) cp_wait<3>();
        else if (c == NCH - 3) cp_wait<2>();
        else if (c == NCH - 2) cp_wait<1>();
        else                   cp_wait<0>();
        __syncthreads();   // stage c fully visible to all warps

        if (c + 5 < NCH) issue(c + 5, (c + 5) % NSTAGE);

        const uint32_t stg = sb + SM_BUF + (c % NSTAGE) * STG_SZ;

#pragma unroll
        for (int s = 0; s < 2; s++) {
            uint32_t xf[4][4], wf[2][4];
            const uint32_t kcol = (uint32_t)(s * 32);
#pragma unroll
            for (int fi = 0; fi < 4; fi++)
                ldsm4(xf[fi], stg + a_off[fi] + ((kcol + a_klane) ^ a_mask[fi]));
#pragma unroll
            for (int jp = 0; jp < 2; jp++)
                ldsm4(wf[jp], stg + b_off[jp] + ((kcol + b_klane) ^ b_mask[jp]));
#pragma unroll
            for (int fi = 0; fi < 4; fi++) {
#pragma unroll
                for (int j = 0; j < 4; j++) {
                    mma16816(acc[fi][j], xf[fi], &wf[j >> 1][(j & 1) * 2]);
                }
            }
        }
    }

    // ---- epilogue: direct register->gmem scatter (32B-sector coalesced) ----
    // mma fragment layout: thread (lane) holds rows {aw+fi*16 + lane/4, +8},
    // cols {bw + j*8 + (lane%4)*2 + 0,1}. Lanes 0..3 of a row-group cover 8
    // consecutive cols -> each float2 store lands in a full 32B sector.
    {
        const int r_in = lane >> 2;          // 0..7
        const int c_in = (lane & 3) * 2;     // 0,2,4,6

        float* optr[8];
        bool   vld[8];
#pragma unroll
        for (int fi = 0; fi < 4; fi++) {
#pragma unroll
            for (int h = 0; h < 2; h++) {
                const int row = aw + fi * 16 + h * 8 + r_in;
                const bool v = (m0 + row) < cnt;
                vld[fi * 2 + h] = v;
                const int tok = stok[row];
                optr[fi * 2 + h] = out + (size_t)tok * OUT_F + n0 + bw + c_in;
            }
        }

        float2 bv[4];
#pragma unroll
        for (int j = 0; j < 4; j++)
            bv[j] = *(const float2*)&sbias[bw + j * 8 + c_in];

#pragma unroll
        for (int fi = 0; fi < 4; fi++) {
#pragma unroll
            for (int j = 0; j < 4; j++) {
                if (vld[fi * 2 + 0]) {
                    float2 v = make_float2(acc[fi][j][0] + bv[j].x,
                                           acc[fi][j][1] + bv[j].y);
                    *(float2*)(optr[fi * 2 + 0] + j * 8) = v;
                }
                if (vld[fi * 2 + 1]) {
                    float2 v = make_float2(acc[fi][j][2] + bv[j].x,
                                           acc[fi][j][3] + bv[j].y);
                    *(float2*)(optr[fi * 2 + 1] + j * 8) = v;
                }
            }
        }
    }
}

// ---------------- launch ----------------
extern "C" void kernel_launch(void* const* d_in, const int* in_sizes, int n_in,
                              void* d_out, int out_size) {
    const float* x    = (const float*)d_in[0];
    const float* wght = (const float*)d_in[1];
    const float* bias = (const float*)d_in[2];
    const int*   eid  = (const int*)d_in[3];
    float* out = (float*)d_out;

    cudaFuncSetAttribute(k_gemm, cudaFuncAttributeMaxDynamicSharedMemorySize,
                         SMEM_TOTAL);

    __half* wf;
    cudaGetSymbolAddress((void**)&wf, g_wf);

    k_zero<<<1, 64>>>();
    k_route<<<NTOK / RBLK, RBLK>>>(x, eid, out);

    const int nw16 = NUM_E * OUT_F * IN_F / 16;      // 1048576
    k_cvt<<<nw16 / 256, 256>>>(wght, wf, nw16);

    dim3 grid(MTILES * NTILES, NUM_E);
    k_gemm<<<grid, THREADS, SMEM_TOTAL>>>(bias, out);
}

// round 16
// speedup vs baseline: 1.3802x; 1.0468x over previous
#include <cuda_runtime.h>
#include <cuda_fp16.h>
#include <cstdint>

// ---------------- problem constants ----------------
#define NUM_E    64
#define IN_F     512
#define OUT_F    512
#define NTOK     131072
#define CAPACITY 3072

// ---------------- tiling ----------------
#define TM 128
#define TN 128
#define KC 64                  // K chunk (64 fp16 = 128B row)
#define NCH (IN_F / KC)        // 8
#define THREADS 256            // 8 warps, warp tile 64x32 (2 M-groups x 4 N-groups)
#define NSTAGE 3
#define NTILES (OUT_F / TN)    // 4
#define MTILES (CAPACITY / TM) // 24

// ---------------- smem layout (bytes) ----------------
#define SM_TOK   0                       // 128 ints
#define SM_BIAS  512                     // 128 floats
#define SM_BUF   1024
#define TILE_X   (TM * KC * 2)           // 16384
#define TILE_W   (TN * KC * 2)           // 16384
#define STG_SZ   (TILE_X + TILE_W)       // 32768
#define SMEM_TOTAL (SM_BUF + NSTAGE * STG_SZ)   // 99328 (x2 CTAs = 194KB)

// SW128 swizzle for 128B rows
#define SWZ(off) ((off) ^ (((off) >> 3) & 0x70))

__device__ int g_cnt[NUM_E];
__device__ int g_tok[NUM_E * CAPACITY];   // slot -> token id

// fp16 operands: xg permuted by expert slot; wf expert-major
__device__ __half g_xg[(size_t)NUM_E * CAPACITY * IN_F]; // 192 MB
__device__ __half g_wf[(size_t)NUM_E * OUT_F * IN_F];    // 32 MB

// ---------------- PTX helpers ----------------
__device__ __forceinline__ uint32_t smem_u32(const void* p) {
    uint32_t a;
    asm("{ .reg .u64 t; cvta.to.shared.u64 t, %1; cvt.u32.u64 %0, t; }"
        : "=r"(a) : "l"(p));
    return a;
}
__device__ __forceinline__ void cp16(uint32_t dst, const void* src) {
    asm volatile("cp.async.cg.shared.global [%0], [%1], 16;"
                 :: "r"(dst), "l"(src));
}
__device__ __forceinline__ void cp_commit() {
    asm volatile("cp.async.commit_group;" ::: "memory");
}
template <int N>
__device__ __forceinline__ void cp_wait() {
    asm volatile("cp.async.wait_group %0;" :: "n"(N) : "memory");
}
__device__ __forceinline__ void ldsm4(uint32_t* r, uint32_t a) {
    asm volatile("ldmatrix.sync.aligned.m8n8.x4.shared.b16 {%0,%1,%2,%3}, [%4];"
                 : "=r"(r[0]), "=r"(r[1]), "=r"(r[2]), "=r"(r[3]) : "r"(a));
}
__device__ __forceinline__ void mma16816(float* d, const uint32_t* a,
                                         const uint32_t* b) {
    asm volatile(
        "mma.sync.aligned.m16n8k16.row.col.f32.f16.f16.f32 "
        "{%0,%1,%2,%3}, {%4,%5,%6,%7}, {%8,%9}, {%0,%1,%2,%3};"
        : "+f"(d[0]), "+f"(d[1]), "+f"(d[2]), "+f"(d[3])
        : "r"(a[0]), "r"(a[1]), "r"(a[2]), "r"(a[3]), "r"(b[0]), "r"(b[1]));
}

// fp32x16 -> fp16x16 pack
__device__ __forceinline__ void cvt16(const float4* v, uint32_t* H) {
    const float* f = (const float*)v;
#pragma unroll
    for (int j = 0; j < 8; j++) {
        __half h0 = __float2half_rn(f[2 * j]);
        __half h1 = __float2half_rn(f[2 * j + 1]);
        H[j] = ((uint32_t)__half_as_ushort(h1) << 16) | __half_as_ushort(h0);
    }
}

// ---------------- pre-pass: w -> fp16 (+ counter zero in block 0) ----------
__global__ __launch_bounds__(256)
void k_cvt(const float* __restrict__ src, __half* __restrict__ dst, int n16) {
    if (blockIdx.x == 0 && threadIdx.x < NUM_E) g_cnt[threadIdx.x] = 0;
    int g = blockIdx.x * blockDim.x + threadIdx.x;
    if (g >= n16) return;
    const float4* s = (const float4*)(src + (size_t)g * 16);
    float4 v[4] = {s[0], s[1], s[2], s[3]};
    uint32_t H[8];
    cvt16(v, H);
    uint4* d = (uint4*)(dst + (size_t)g * 16);
    d[0] = make_uint4(H[0], H[1], H[2], H[3]);
    d[1] = make_uint4(H[4], H[5], H[6], H[7]);
}

// ---------------- fused route + x->fp16 permuted write ----------------
#define RBLK 256
__global__ __launch_bounds__(RBLK)
void k_route(const float* __restrict__ x, const int* __restrict__ eid,
             float* __restrict__ out) {
    __shared__ int s_slot[RBLK];
    __shared__ int s_hist[NUM_E];
    __shared__ int s_base[NUM_E];
    __shared__ int s_cur[NUM_E];

    const int tid = threadIdx.x;
    const int t0  = blockIdx.x * RBLK;

    int e = eid[t0 + tid];
    if (tid < NUM_E) { s_hist[tid] = 0; s_cur[tid] = 0; }
    __syncthreads();
    atomicAdd(&s_hist[e], 1);
    __syncthreads();
    if (tid < NUM_E) {
        int h = s_hist[tid];
        s_base[tid] = h ? atomicAdd(&g_cnt[tid], h) : 0;
    }
    __syncthreads();
    {
        int r = s_base[e] + atomicAdd(&s_cur[e], 1);
        if (r < CAPACITY) {
            int slot = e * CAPACITY + r;
            g_tok[slot] = t0 + tid;
            s_slot[tid] = slot;
        } else {
            s_slot[tid] = -1;
        }
    }
    __syncthreads();

    const int lane = tid & 31;
    const int wrp  = tid >> 5;
#pragma unroll 4
    for (int i = 0; i < 32; i++) {
        const int row = wrp * 32 + i;
        const int slot = s_slot[row];
        const float* src = x + (size_t)(t0 + row) * IN_F + lane * 16;
        if (slot >= 0) {
            float4 v[4] = {*(const float4*)(src + 0), *(const float4*)(src + 4),
                           *(const float4*)(src + 8), *(const float4*)(src + 12)};
            uint32_t H[8];
            cvt16(v, H);
            uint4* d = (uint4*)(g_xg + (size_t)slot * IN_F + lane * 16);
            d[0] = make_uint4(H[0], H[1], H[2], H[3]);
            d[1] = make_uint4(H[4], H[5], H[6], H[7]);
        } else {
            float4 z = make_float4(0.f, 0.f, 0.f, 0.f);
            float4* o = (float4*)(out + (size_t)(t0 + row) * OUT_F + lane * 16);
            o[0] = z; o[1] = z; o[2] = z; o[3] = z;
        }
    }
}

// ---------------- main GEMM: 128x128 tile, 8 warps (64x32), 2 CTAs/SM ----------------
__global__ __launch_bounds__(THREADS, 2)
void k_gemm(const float* __restrict__ bias, float* __restrict__ out) {
    extern __shared__ char smem[];

    const int e = blockIdx.y;
    int cnt = g_cnt[e];
    if (cnt > CAPACITY) cnt = CAPACITY;
    const int m0 = (blockIdx.x >> 2) * TM;
    if (m0 >= cnt) return;
    const int n0 = (blockIdx.x & 3) * TN;

    const int tid  = threadIdx.x;
    const int lane = tid & 31;
    const int wid  = tid >> 5;

    int*   stok  = (int*)(smem + SM_TOK);
    float* sbias = (float*)(smem + SM_BIAS);

    if (tid < TM) {
        stok[tid] = (m0 + tid < cnt) ? g_tok[e * CAPACITY + m0 + tid] : 0;
    } else {
        sbias[tid - TM] = bias[e * OUT_F + n0 + (tid - TM)];
    }
    __syncthreads();

    const uint32_t sb = smem_u32(smem);
    const size_t xrow0 = (size_t)(e * CAPACITY + m0) * IN_F;
    const size_t wrow0 = ((size_t)e * OUT_F + n0) * IN_F;

    // cp.async: 2048 x 16B granules per stage (X 1024 + W 1024), 8 per thread
    auto issue = [&](int c, int st) {
        const uint32_t stg = sb + SM_BUF + st * STG_SZ;
        const int k0 = c * KC;
#pragma unroll
        for (int i = 0; i < 8; i++) {
            int g = tid + i * THREADS;              // 0..2047
            if (g < 1024) {
                int row = g >> 3, c8 = g & 7;
                uint32_t dst = stg + SWZ((uint32_t)(row * 128 + c8 * 16));
                cp16(dst, g_xg + xrow0 + (size_t)row * IN_F + k0 + c8 * 8);
            } else {
                int gw = g - 1024;
                int row = gw >> 3, c8 = gw & 7;
                uint32_t dst = stg + TILE_X + SWZ((uint32_t)(row * 128 + c8 * 16));
                cp16(dst, g_wf + wrow0 + (size_t)row * IN_F + k0 + c8 * 8);
            }
        }
        cp_commit();
    };

    // per-warp ldmatrix address precompute (stage-relative, 128B rows)
    const int aw = (wid >> 2) * 64;  // warp M offset: 2 groups of 64
    const int bw = (wid & 3) * 32;   // warp N offset: 4 groups of 32

    uint32_t a_off[4], a_mask[4];
    {
        int ar = lane & 15;
#pragma unroll
        for (int fi = 0; fi < 4; fi++) {
            int r = aw + fi * 16 + ar;
            a_off[fi] = (uint32_t)(r * 128);
            a_mask[fi] = (r & 7) * 16;
        }
    }
    const uint32_t a_klane = (lane & 16) ? 16u : 0u;

    uint32_t b_off[2], b_mask[2];
    {
        int br = (lane & 7) + ((lane & 16) ? 8 : 0);
#pragma unroll
        for (int jp = 0; jp < 2; jp++) {
            int r = bw + jp * 16 + br;
            b_off[jp] = (uint32_t)(TILE_X + r * 128);
            b_mask[jp] = (r & 7) * 16;
        }
    }
    const uint32_t b_klane = (lane & 8) ? 16u : 0u;

    float acc[4][4][4];
#pragma unroll
    for (int i = 0; i < 4; i++)
#pragma unroll
        for (int j = 0; j < 4; j++)
#pragma unroll
            for (int q = 0; q < 4; q++) acc[i][j][q] = 0.f;

    // ---- pipeline: 3 buffers, 2 chunks in flight ----
    issue(0, 0);
    issue(1, 1);

#pragma unroll
    for (int c = 0; c < NCH; c++) {
        if (c < NCH - 1) cp_wait<1>(); else cp_wait<0>();
        __syncthreads();   // stage c fully visible to all warps

        // refill stage (c+2)%3 = (c-1)%3; readers are past the barrier
        if (c + 2 < NCH) issue(c + 2, (c + 2) % NSTAGE);

        const uint32_t stg = sb + SM_BUF + (c % NSTAGE) * STG_SZ;

#pragma unroll
        for (int s = 0; s < 4; s++) {
            uint32_t xf[4][4], wf[2][4];
            const uint32_t kcol = (uint32_t)(s * 32);
#pragma unroll
            for (int fi = 0; fi < 4; fi++)
                ldsm4(xf[fi], stg + a_off[fi] + ((kcol + a_klane) ^ a_mask[fi]));
#pragma unroll
            for (int jp = 0; jp < 2; jp++)
                ldsm4(wf[jp], stg + b_off[jp] + ((kcol + b_klane) ^ b_mask[jp]));
#pragma unroll
            for (int fi = 0; fi < 4; fi++) {
#pragma unroll
                for (int j = 0; j < 4; j++) {
                    mma16816(acc[fi][j], xf[fi], &wf[j >> 1][(j & 1) * 2]);
                }
            }
        }
    }

    // ---- epilogue: direct register->gmem scatter (32B-sector coalesced) ----
    {
        const int r_in = lane >> 2;          // 0..7
        const int c_in = (lane & 3) * 2;     // 0,2,4,6

        float* optr[8];
        bool   vld[8];
#pragma unroll
        for (int fi = 0; fi < 4; fi++) {
#pragma unroll
            for (int h = 0; h < 2; h++) {
                const int row = aw + fi * 16 + h * 8 + r_in;
                vld[fi * 2 + h] = (m0 + row) < cnt;
                const int tok = stok[row];
                optr[fi * 2 + h] = out + (size_t)tok * OUT_F + n0 + bw + c_in;
            }
        }

        float2 bv[4];
#pragma unroll
        for (int j = 0; j < 4; j++)
            bv[j] = *(const float2*)&sbias[bw + j * 8 + c_in];

#pragma unroll
        for (int fi = 0; fi < 4; fi++) {
#pragma unroll
            for (int j = 0; j < 4; j++) {
                if (vld[fi * 2 + 0]) {
                    float2 v = make_float2(acc[fi][j][0] + bv[j].x,
                                           acc[fi][j][1] + bv[j].y);
                    *(float2*)(optr[fi * 2 + 0] + j * 8) = v;
                }
                if (vld[fi * 2 + 1]) {
                    float2 v = make_float2(acc[fi][j][2] + bv[j].x,
                                           acc[fi][j][3] + bv[j].y);
                    *(float2*)(optr[fi * 2 + 1] + j * 8) = v;
                }
            }
        }
    }
}

// ---------------- launch ----------------
extern "C" void kernel_launch(void* const* d_in, const int* in_sizes, int n_in,
                              void* d_out, int out_size) {
    const float* x    = (const float*)d_in[0];
    const float* wght = (const float*)d_in[1];
    const float* bias = (const float*)d_in[2];
    const int*   eid  = (const int*)d_in[3];
    float* out = (float*)d_out;

    cudaFuncSetAttribute(k_gemm, cudaFuncAttributeMaxDynamicSharedMemorySize,
                         SMEM_TOTAL);

    __half* wf;
    cudaGetSymbolAddress((void**)&wf, g_wf);

    // k_cvt block 0 zeros g_cnt; k_route (stream-ordered after) sees zeros.
    const int nw16 = NUM_E * OUT_F * IN_F / 16;      // 1048576
    k_cvt<<<nw16 / 256, 256>>>(wght, wf, nw16);

    k_route<<<NTOK / RBLK, RBLK>>>(x, eid, out);

    dim3 grid(MTILES * NTILES, NUM_E);
    k_gemm<<<grid, THREADS, SMEM_TOTAL>>>(bias, out);
}